// round 2
// baseline (speedup 1.0000x reference)
#include <cuda_runtime.h>
#include <math.h>

#define BB 4
#define CC 192
#define C2 384
#define HWN 16384
#define HIMG 128
#define NHEADS 4
#define CHD 48
#define HIDC 510
#define HID2 1020
#define EPSLN 1e-5f

// ---------------- scratch (static device memory; no runtime alloc) ----------
__device__ float g_xn  [BB*CC*HWN];
__device__ float g_kv1n[BB*CC*HWN];
__device__ float g_kv2n[BB*CC*HWN];
__device__ float g_qpre [BB*C2*HWN];
__device__ float g_kv1pre[BB*C2*HWN];
__device__ float g_kv2pre[BB*C2*HWN];
__device__ float g_q   [BB*C2*HWN];
__device__ float g_kv1 [BB*C2*HWN];
__device__ float g_kv2 [BB*C2*HWN];
__device__ float g_ao  [BB*C2*HWN];
__device__ float g_x2  [BB*CC*HWN];
__device__ float g_h   [BB*HID2*HWN];
__device__ float g_hd  [BB*HID2*HWN];
__device__ float g_gg  [BB*HIDC*HWN];
__device__ float g_S   [32*CHD*CHD];
__device__ float g_nrm [32*2*CHD];

// ---------------- LayerNorm over channel dim, NCHW ----------------
__global__ void ln_kernel(const float* __restrict__ X, const float* __restrict__ w,
                          const float* __restrict__ bia, float* __restrict__ Y) {
    int b = blockIdx.y;
    int p = blockIdx.x * 256 + threadIdx.x;
    const float* xp = X + (size_t)b * CC * HWN + p;
    float mu = 0.f;
    #pragma unroll 4
    for (int c = 0; c < CC; c++) mu += xp[(size_t)c * HWN];
    mu *= (1.f / CC);
    float var = 0.f;
    #pragma unroll 4
    for (int c = 0; c < CC; c++) { float d = xp[(size_t)c * HWN] - mu; var += d * d; }
    var *= (1.f / CC);
    float inv = rsqrtf(var + EPSLN);
    float* yp = Y + (size_t)b * CC * HWN + p;
    #pragma unroll 4
    for (int c = 0; c < CC; c++)
        yp[(size_t)c * HWN] = (xp[(size_t)c * HWN] - mu) * inv * w[c] + bia[c];
}

// ---------------- 1x1 conv as SGEMM: Y[b][o][p] = sum_c W[o][c] X[b][c][p] ---
template<bool RESID>
__global__ void gemm1x1(const float* __restrict__ W, const float* __restrict__ X,
                        const float* __restrict__ R, float* __restrict__ Y,
                        int O, int Cin) {
    const int BM = 128, BN = 128, BK = 8;
    __shared__ float As[BK][BM];
    __shared__ float Bs[BK][BN + 4];
    int b  = blockIdx.z;
    int p0 = blockIdx.x * BN;
    int o0 = blockIdx.y * BM;
    int t  = threadIdx.x;
    int tm = (t >> 4) * 8;
    int tn = (t & 15) * 8;
    float acc[8][8];
    #pragma unroll
    for (int i = 0; i < 8; i++)
        #pragma unroll
        for (int j = 0; j < 8; j++) acc[i][j] = 0.f;

    const float* Xb = X + (size_t)b * Cin * HWN;
    for (int k0 = 0; k0 < Cin; k0 += BK) {
        #pragma unroll
        for (int i = t; i < BM * BK; i += 256) {
            int m = i >> 3, k = i & 7;
            int o = o0 + m, c = k0 + k;
            As[k][m] = (o < O && c < Cin) ? W[(size_t)o * Cin + c] : 0.f;
        }
        #pragma unroll
        for (int i = t; i < BK * BN; i += 256) {
            int k = i >> 7, n = i & 127;
            int c = k0 + k;
            Bs[k][n] = (c < Cin) ? Xb[(size_t)c * HWN + p0 + n] : 0.f;
        }
        __syncthreads();
        #pragma unroll
        for (int k = 0; k < BK; k++) {
            float ra[8], rb[8];
            #pragma unroll
            for (int i = 0; i < 8; i++) ra[i] = As[k][tm + i];
            #pragma unroll
            for (int j = 0; j < 8; j++) rb[j] = Bs[k][tn + j];
            #pragma unroll
            for (int i = 0; i < 8; i++)
                #pragma unroll
                for (int j = 0; j < 8; j++) acc[i][j] += ra[i] * rb[j];
        }
        __syncthreads();
    }
    float* Yb = Y + (size_t)b * O * HWN;
    const float* Rb = R + (size_t)b * O * HWN;
    #pragma unroll
    for (int i = 0; i < 8; i++) {
        int o = o0 + tm + i;
        if (o >= O) break;
        #pragma unroll
        for (int j = 0; j < 8; j++) {
            int p = p0 + tn + j;
            float v = acc[i][j];
            if (RESID) v += Rb[(size_t)o * HWN + p];
            Yb[(size_t)o * HWN + p] = v;
        }
    }
}

// ---------------- depthwise 3x3, 1 channel per group ----------------
__global__ void dwconv_dw(const float* __restrict__ X, const float* __restrict__ Wt,
                          float* __restrict__ Y, int Ctot) {
    int b = blockIdx.z, c = blockIdx.y;
    int p = blockIdx.x * 256 + threadIdx.x;
    int h = p >> 7, w = p & (HIMG - 1);
    const float* xp = X + ((size_t)b * Ctot + c) * HWN;
    const float* wp = Wt + (size_t)c * 9;
    float s = 0.f;
    #pragma unroll
    for (int dy = -1; dy <= 1; dy++) {
        int hh = h + dy;
        if (hh < 0 || hh >= HIMG) continue;
        #pragma unroll
        for (int dx = -1; dx <= 1; dx++) {
            int ww = w + dx;
            if (ww < 0 || ww >= HIMG) continue;
            s += wp[(dy + 1) * 3 + (dx + 1)] * xp[hh * HIMG + ww];
        }
    }
    Y[((size_t)b * Ctot + c) * HWN + p] = s;
}

// ---------------- grouped 3x3, groups=192, 2 in / 2 out per group -----------
__global__ void dwconv_g2(const float* __restrict__ X, const float* __restrict__ Wt,
                          float* __restrict__ Y) {
    int b = blockIdx.z, o = blockIdx.y;  // o in [0,384)
    int p = blockIdx.x * 256 + threadIdx.x;
    int h = p >> 7, w = p & (HIMG - 1);
    int i0 = (o >> 1) << 1;
    const float* x0 = X + ((size_t)b * C2 + i0) * HWN;
    const float* wp = Wt + (size_t)o * 18;
    float s = 0.f;
    #pragma unroll
    for (int ic = 0; ic < 2; ic++) {
        const float* xp = x0 + (size_t)ic * HWN;
        const float* wq = wp + ic * 9;
        #pragma unroll
        for (int dy = -1; dy <= 1; dy++) {
            int hh = h + dy;
            if (hh < 0 || hh >= HIMG) continue;
            #pragma unroll
            for (int dx = -1; dx <= 1; dx++) {
                int ww = w + dx;
                if (ww < 0 || ww >= HIMG) continue;
                s += wq[(dy + 1) * 3 + (dx + 1)] * xp[hh * HIMG + ww];
            }
        }
    }
    Y[((size_t)b * C2 + o) * HWN + p] = s;
}

// ---------------- attention helpers ----------------
__global__ void zero_S() {
    int i = blockIdx.x * 256 + threadIdx.x;
    if (i < 32 * CHD * CHD) g_S[i] = 0.f;
}

// row L2 norms of q (rows 0..47) and k (rows 48..95) per matrix m
__global__ void rownorm_kernel() {
    int m = blockIdx.x;       // 0..31
    int r = blockIdx.y;       // 0..95
    int b = m >> 3, br = (m >> 2) & 1, hh = m & 3;
    const float* base;
    if (r < CHD) {
        base = g_q + ((size_t)b * C2 + br * CC + hh * CHD + r) * HWN;
    } else {
        const float* src = br ? g_kv2 : g_kv1;
        base = src + ((size_t)b * C2 + hh * CHD + (r - CHD)) * HWN;
    }
    __shared__ float red[256];
    float s = 0.f;
    for (int i = threadIdx.x; i < HWN; i += 256) { float v = base[i]; s += v * v; }
    red[threadIdx.x] = s;
    __syncthreads();
    for (int st = 128; st > 0; st >>= 1) {
        if (threadIdx.x < st) red[threadIdx.x] += red[threadIdx.x + st];
        __syncthreads();
    }
    if (threadIdx.x == 0) g_nrm[m * 96 + r] = fmaxf(sqrtf(red[0]), 1e-12f);
}

// raw logits S[m][c][d] = q_c . k_d  (split-K over n, atomics)
__global__ void skernel() {
    int m = blockIdx.x, ns = blockIdx.y;   // 32 x 16
    int b = m >> 3, br = (m >> 2) & 1, hh = m & 3;
    const float* qb = g_q + ((size_t)b * C2 + br * CC + hh * CHD) * HWN;
    const float* kb = (br ? g_kv2 : g_kv1) + ((size_t)b * C2 + hh * CHD) * HWN;
    __shared__ float Qs[CHD][65];
    __shared__ float Ks[CHD][65];
    int t = threadIdx.x;
    int tx = t & 15, ty = t >> 4;
    float acc[3][3];
    #pragma unroll
    for (int i = 0; i < 3; i++)
        #pragma unroll
        for (int j = 0; j < 3; j++) acc[i][j] = 0.f;
    int nbeg = ns * 1024;
    for (int n0 = nbeg; n0 < nbeg + 1024; n0 += 64) {
        #pragma unroll
        for (int i = t; i < CHD * 64; i += 256) {
            int rr = i >> 6, cc = i & 63;
            Qs[rr][cc] = qb[(size_t)rr * HWN + n0 + cc];
            Ks[rr][cc] = kb[(size_t)rr * HWN + n0 + cc];
        }
        __syncthreads();
        #pragma unroll 8
        for (int kk = 0; kk < 64; kk++) {
            float qv[3], kv[3];
            #pragma unroll
            for (int i = 0; i < 3; i++) qv[i] = Qs[ty + 16 * i][kk];
            #pragma unroll
            for (int j = 0; j < 3; j++) kv[j] = Ks[tx + 16 * j][kk];
            #pragma unroll
            for (int i = 0; i < 3; i++)
                #pragma unroll
                for (int j = 0; j < 3; j++) acc[i][j] += qv[i] * kv[j];
        }
        __syncthreads();
    }
    #pragma unroll
    for (int i = 0; i < 3; i++)
        #pragma unroll
        for (int j = 0; j < 3; j++)
            atomicAdd(&g_S[m * CHD * CHD + (ty + 16 * i) * CHD + (tx + 16 * j)], acc[i][j]);
}

__global__ void softmax_kernel(const float* __restrict__ t1, const float* __restrict__ t2) {
    int m = blockIdx.x;
    int c = threadIdx.x;
    if (c >= CHD) return;
    int br = (m >> 2) & 1, hh = m & 3;
    float tmp = (br ? t2 : t1)[hh];
    float nq = g_nrm[m * 96 + c];
    float* row = g_S + (size_t)m * CHD * CHD + c * CHD;
    float vals[CHD];
    float mx = -1e30f;
    #pragma unroll
    for (int d = 0; d < CHD; d++) {
        float v = row[d] / (nq * g_nrm[m * 96 + CHD + d]) * tmp;
        vals[d] = v;
        mx = fmaxf(mx, v);
    }
    float sum = 0.f;
    #pragma unroll
    for (int d = 0; d < CHD; d++) { vals[d] = __expf(vals[d] - mx); sum += vals[d]; }
    float inv = 1.f / sum;
    #pragma unroll
    for (int d = 0; d < CHD; d++) row[d] = vals[d] * inv;
}

// out[c][p] = sum_d A[c][d] * v[d][p]
__global__ void av_kernel() {
    int m = blockIdx.x;
    int b = m >> 3, br = (m >> 2) & 1, hh = m & 3;
    __shared__ float As[CHD * CHD];
    for (int i = threadIdx.x; i < CHD * CHD; i += 128) As[i] = g_S[(size_t)m * CHD * CHD + i];
    __syncthreads();
    const float* vb = (br ? g_kv2 : g_kv1) + ((size_t)b * C2 + CC + hh * CHD) * HWN;
    float* ob = g_ao + ((size_t)b * C2 + br * CC + hh * CHD) * HWN;
    int p = blockIdx.y * 256 + threadIdx.x;
    float acc0[CHD], acc1[CHD];
    #pragma unroll
    for (int c = 0; c < CHD; c++) { acc0[c] = 0.f; acc1[c] = 0.f; }
    for (int d = 0; d < CHD; d++) {
        float v0 = vb[(size_t)d * HWN + p];
        float v1 = vb[(size_t)d * HWN + p + 128];
        #pragma unroll
        for (int c = 0; c < CHD; c++) {
            float a = As[c * CHD + d];
            acc0[c] += a * v0;
            acc1[c] += a * v1;
        }
    }
    #pragma unroll
    for (int c = 0; c < CHD; c++) {
        ob[(size_t)c * HWN + p] = acc0[c];
        ob[(size_t)c * HWN + p + 128] = acc1[c];
    }
}

// ---------------- gated gelu ----------------
__global__ void gelu_gate() {
    int b = blockIdx.z, c = blockIdx.y;
    int p = blockIdx.x * 256 + threadIdx.x;
    float a = g_hd[((size_t)b * HID2 + c) * HWN + p];
    float g = g_hd[((size_t)b * HID2 + HIDC + c) * HWN + p];
    float ge = 0.5f * a * (1.f + erff(a * 0.70710678118654752f));
    g_gg[((size_t)b * HIDC + c) * HWN + p] = ge * g;
}

// ---------------- launch ----------------
extern "C" void kernel_launch(void* const* d_in, const int* in_sizes, int n_in,
                              void* d_out, int out_size) {
    const float* x       = (const float*)d_in[0];
    const float* kv1in   = (const float*)d_in[1];
    const float* kv2in   = (const float*)d_in[2];
    const float* n1w = (const float*)d_in[3];  const float* n1b = (const float*)d_in[4];
    const float* nk1w = (const float*)d_in[5]; const float* nk1b = (const float*)d_in[6];
    const float* nk2w = (const float*)d_in[7]; const float* nk2b = (const float*)d_in[8];
    const float* n2w = (const float*)d_in[9];  const float* n2b = (const float*)d_in[10];
    const float* q_w   = (const float*)d_in[11];
    const float* kv1_w = (const float*)d_in[12];
    const float* kv2_w = (const float*)d_in[13];
    const float* q_dw  = (const float*)d_in[14];
    const float* kv1_dw= (const float*)d_in[15];
    const float* kv2_dw= (const float*)d_in[16];
    const float* proj_w= (const float*)d_in[17];
    const float* temp1 = (const float*)d_in[18];
    const float* temp2 = (const float*)d_in[19];
    const float* pin_w = (const float*)d_in[20];
    const float* dw_w  = (const float*)d_in[21];
    const float* pout_w= (const float*)d_in[22];
    float* out = (float*)d_out;

    float *p_xn, *p_kv1n, *p_kv2n, *p_qpre, *p_kv1pre, *p_kv2pre;
    float *p_q, *p_kv1, *p_kv2, *p_ao, *p_x2, *p_h, *p_hd, *p_gg;
    cudaGetSymbolAddress((void**)&p_xn, g_xn);
    cudaGetSymbolAddress((void**)&p_kv1n, g_kv1n);
    cudaGetSymbolAddress((void**)&p_kv2n, g_kv2n);
    cudaGetSymbolAddress((void**)&p_qpre, g_qpre);
    cudaGetSymbolAddress((void**)&p_kv1pre, g_kv1pre);
    cudaGetSymbolAddress((void**)&p_kv2pre, g_kv2pre);
    cudaGetSymbolAddress((void**)&p_q, g_q);
    cudaGetSymbolAddress((void**)&p_kv1, g_kv1);
    cudaGetSymbolAddress((void**)&p_kv2, g_kv2);
    cudaGetSymbolAddress((void**)&p_ao, g_ao);
    cudaGetSymbolAddress((void**)&p_x2, g_x2);
    cudaGetSymbolAddress((void**)&p_h, g_h);
    cudaGetSymbolAddress((void**)&p_hd, g_hd);
    cudaGetSymbolAddress((void**)&p_gg, g_gg);

    dim3 lnG(HWN / 256, BB);
    ln_kernel<<<lnG, 256>>>(x, n1w, n1b, p_xn);
    ln_kernel<<<lnG, 256>>>(kv1in, nk1w, nk1b, p_kv1n);
    ln_kernel<<<lnG, 256>>>(kv2in, nk2w, nk2b, p_kv2n);

    // 1x1 convs: 192 -> 384
    dim3 gQ(HWN / 128, 3, BB);
    gemm1x1<false><<<gQ, 256>>>(q_w,   p_xn,   nullptr, p_qpre,   C2, CC);
    gemm1x1<false><<<gQ, 256>>>(kv1_w, p_kv1n, nullptr, p_kv1pre, C2, CC);
    gemm1x1<false><<<gQ, 256>>>(kv2_w, p_kv2n, nullptr, p_kv2pre, C2, CC);

    // 3x3 grouped / depthwise
    dim3 dG(HWN / 256, C2, BB);
    dwconv_g2<<<dG, 256>>>(p_qpre, q_dw, p_q);
    dwconv_dw<<<dG, 256>>>(p_kv1pre, kv1_dw, p_kv1, C2);
    dwconv_dw<<<dG, 256>>>(p_kv2pre, kv2_dw, p_kv2, C2);

    // channel attention
    zero_S<<<(32 * CHD * CHD + 255) / 256, 256>>>();
    rownorm_kernel<<<dim3(32, 96), 256>>>();
    skernel<<<dim3(32, 16), 256>>>();
    softmax_kernel<<<32, 64>>>(temp1, temp2);
    av_kernel<<<dim3(32, HWN / 256), 128>>>();

    // proj (384 -> 192) + residual x
    dim3 gP(HWN / 128, 2, BB);
    gemm1x1<true><<<gP, 256>>>(proj_w, p_ao, x, p_x2, CC, C2);

    // FFN
    ln_kernel<<<lnG, 256>>>(p_x2, n2w, n2b, p_xn);
    dim3 gIn(HWN / 128, (HID2 + 127) / 128, BB);
    gemm1x1<false><<<gIn, 256>>>(pin_w, p_xn, nullptr, p_h, HID2, CC);
    dim3 dG2(HWN / 256, HID2, BB);
    dwconv_dw<<<dG2, 256>>>(p_h, dw_w, p_hd, HID2);
    dim3 gg(HWN / 256, HIDC, BB);
    gelu_gate<<<gg, 256>>>();
    gemm1x1<true><<<gP, 256>>>(pout_w, p_gg, p_x2, out, CC, HIDC);
}

// round 5
// speedup vs baseline: 2.6750x; 2.6750x over previous
#include <cuda_runtime.h>
#include <cuda_bf16.h>
#include <math.h>

#define BB 4
#define CC 192
#define C2 384
#define HWN 16384
#define HIMG 128
#define CHD 48
#define HIDC 510
#define HID2 1020
#define GGPAD 512
#define EPSLN 1e-5f

__device__ __forceinline__ unsigned smem_u32(const void* p) {
    unsigned a;
    asm("{ .reg .u64 t; cvta.to.shared.u64 t, %1; cvt.u32.u64 %0, t; }"
        : "=r"(a) : "l"(p));
    return a;
}
#define CP_ASYNC16(dst, src) \
    asm volatile("cp.async.cg.shared.global [%0], [%1], 16;" :: "r"(dst), "l"(src))
#define CP_COMMIT() asm volatile("cp.async.commit_group;" ::: "memory")
#define CP_WAIT(n)  asm volatile("cp.async.wait_group %0;" :: "n"(n) : "memory")

__device__ __forceinline__ void ldm_x4(unsigned& r0, unsigned& r1, unsigned& r2, unsigned& r3,
                                       unsigned addr) {
    asm volatile("ldmatrix.sync.aligned.m8n8.x4.shared.b16 {%0,%1,%2,%3}, [%4];"
        : "=r"(r0), "=r"(r1), "=r"(r2), "=r"(r3) : "r"(addr));
}
__device__ __forceinline__ void mma_bf(float* d, const unsigned* a, unsigned b0, unsigned b1) {
    asm volatile("mma.sync.aligned.m16n8k16.row.col.f32.bf16.bf16.f32 "
        "{%0,%1,%2,%3}, {%4,%5,%6,%7}, {%8,%9}, {%0,%1,%2,%3};"
        : "+f"(d[0]), "+f"(d[1]), "+f"(d[2]), "+f"(d[3])
        : "r"(a[0]), "r"(a[1]), "r"(a[2]), "r"(a[3]), "r"(b0), "r"(b1));
}

// ---------------- scratch ----------------
__device__ float g_qpre [BB*C2*HWN];
__device__ float g_kv1pre[BB*C2*HWN];
__device__ float g_kv2pre[BB*C2*HWN];
__device__ float g_q   [BB*C2*HWN];
__device__ float g_kv1 [BB*C2*HWN];
__device__ float g_kv2 [BB*C2*HWN];
__device__ float g_x2  [BB*CC*HWN];
__device__ float g_h   [BB*HID2*HWN];
__device__ float g_hd  [BB*HID2*HWN];
__device__ float g_S   [32*CHD*CHD];
__device__ float g_nrm [32*2*CHD];

// transposed bf16 hi/lo activations: [b][pixel][channel]
__device__ __align__(16) unsigned short xt_a_hi [BB*HWN*CC];
__device__ __align__(16) unsigned short xt_a_lo [BB*HWN*CC];
__device__ __align__(16) unsigned short xt_k1_hi[BB*HWN*CC];
__device__ __align__(16) unsigned short xt_k1_lo[BB*HWN*CC];
__device__ __align__(16) unsigned short xt_k2_hi[BB*HWN*CC];
__device__ __align__(16) unsigned short xt_k2_lo[BB*HWN*CC];
__device__ __align__(16) unsigned short xt_ao_hi[BB*HWN*C2];
__device__ __align__(16) unsigned short xt_ao_lo[BB*HWN*C2];
__device__ __align__(16) unsigned short xt_gg_hi[BB*HWN*GGPAD];
__device__ __align__(16) unsigned short xt_gg_lo[BB*HWN*GGPAD];
// converted weights (row-major [O][Cpad])
#define OFF_Q   0
#define OFF_K1  (384*192)
#define OFF_K2  (2*384*192)
#define OFF_P   (3*384*192)
#define OFF_PIN (3*384*192 + 192*384)
#define OFF_PO  (3*384*192 + 192*384 + 1020*192)
#define WTOT    (3*384*192 + 192*384 + 1020*192 + 192*512)
#define WPAD    (64*512)
__device__ __align__(16) unsigned short g_whi[WTOT + WPAD];
__device__ __align__(16) unsigned short g_wlo[WTOT + WPAD];

// ---------------- fp32 -> bf16 hi/lo pack of 8 ----------------
__device__ __forceinline__ void cvt8(const float* v, uint4& hv, uint4& lv) {
    unsigned h[4], l[4];
    #pragma unroll
    for (int i = 0; i < 4; i++) {
        float a = v[2*i], bfv = v[2*i+1];
        __nv_bfloat16 ha = __float2bfloat16_rn(a), hb = __float2bfloat16_rn(bfv);
        h[i] = (unsigned)__bfloat16_as_ushort(ha) | ((unsigned)__bfloat16_as_ushort(hb) << 16);
        __nv_bfloat16 la = __float2bfloat16_rn(a - __bfloat162float(ha));
        __nv_bfloat16 lb = __float2bfloat16_rn(bfv - __bfloat162float(hb));
        l[i] = (unsigned)__bfloat16_as_ushort(la) | ((unsigned)__bfloat16_as_ushort(lb) << 16);
    }
    hv = make_uint4(h[0], h[1], h[2], h[3]);
    lv = make_uint4(l[0], l[1], l[2], l[3]);
}

__global__ void wconv(const float* __restrict__ W, unsigned short* __restrict__ Hi,
                      unsigned short* __restrict__ Lo, int O, int Cin, int Cpad) {
    int o = blockIdx.x;
    int c0 = threadIdx.x * 8;
    if (c0 >= Cpad) return;
    float v[8];
    #pragma unroll
    for (int j = 0; j < 8; j++) {
        int c = c0 + j;
        v[j] = (c < Cin) ? W[(size_t)o * Cin + c] : 0.f;
    }
    uint4 hv, lv; cvt8(v, hv, lv);
    *(uint4*)(Hi + (size_t)o * Cpad + c0) = hv;
    *(uint4*)(Lo + (size_t)o * Cpad + c0) = lv;
}

// ======================= HMMA GEMM ==========================================
// Y[b][o][p] = sum_c W[o][c] * Xt[b][p][c] (+ residual)
// BM=128 (o), BN=64 (p), BK=32. 8 warps: 4 (m) x 2 (n), warp tile 32x32.
// 3-term bf16 hi/lo split accumulated in fp32.
#define BK 32
#define ASTRIDE 40                       // halves per smem row (conflict-free)
#define A_BYTES (128 * ASTRIDE * 2)      // 10240
#define B_BYTES (64 * ASTRIDE * 2)       // 5120
#define BUF_BYTES (2 * A_BYTES + 2 * B_BYTES)   // 30720
#define GEMM_SMEM (2 * BUF_BYTES)        // 61440
#define YSTRIDE 68                       // floats; 272B = 16*17 -> float4-aligned rows

template<bool RESID>
__global__ __launch_bounds__(256)
void gemm_mma(const unsigned short* __restrict__ Whi, const unsigned short* __restrict__ Wlo,
              const unsigned short* __restrict__ Xhi, const unsigned short* __restrict__ Xlo,
              const float* __restrict__ R, float* __restrict__ Y, int O, int Cpad) {
    extern __shared__ char dsm[];
    unsigned sbase = smem_u32(dsm);
    int t = threadIdx.x, wid = t >> 5, lane = t & 31;
    int b  = blockIdx.z;
    int p0 = blockIdx.x * 64;
    int o0 = blockIdx.y * 128;
    int warpM = (wid >> 1) * 32;
    int warpN = (wid & 1) * 32;

    const unsigned short* WhiB = Whi + (size_t)o0 * Cpad;
    const unsigned short* WloB = Wlo + (size_t)o0 * Cpad;
    const unsigned short* XhiB = Xhi + ((size_t)b * HWN + p0) * Cpad;
    const unsigned short* XloB = Xlo + ((size_t)b * HWN + p0) * Cpad;

    int nk = Cpad / BK;

    auto fill = [&](int kt) {
        int buf = kt & 1;
        unsigned bb = sbase + buf * BUF_BYTES;
        int k0 = kt * BK;
        #pragma unroll
        for (int j = 0; j < 6; j++) {
            int ci = j * 256 + t;
            if (ci < 1024) {
                int m = ci & 511;
                int row = m >> 2, g = m & 3;
                const unsigned short* src = ((ci < 512) ? WhiB : WloB)
                                            + (size_t)row * Cpad + k0 + g * 8;
                unsigned dst = bb + ((ci < 512) ? 0u : A_BYTES)
                             + (unsigned)(row * ASTRIDE + g * 8) * 2;
                CP_ASYNC16(dst, src);
            } else {
                int m = (ci - 1024) & 255;
                int row = m >> 2, g = m & 3;
                const unsigned short* src = ((ci < 1280) ? XhiB : XloB)
                                            + (size_t)row * Cpad + k0 + g * 8;
                unsigned dst = bb + 2 * A_BYTES + ((ci < 1280) ? 0u : B_BYTES)
                             + (unsigned)(row * ASTRIDE + g * 8) * 2;
                CP_ASYNC16(dst, src);
            }
        }
        CP_COMMIT();
    };

    float acc[2][4][4];
    #pragma unroll
    for (int i = 0; i < 2; i++)
        #pragma unroll
        for (int j = 0; j < 4; j++)
            #pragma unroll
            for (int k = 0; k < 4; k++) acc[i][j][k] = 0.f;

    fill(0);

    for (int kt = 0; kt < nk; kt++) {
        if (kt + 1 < nk) { fill(kt + 1); CP_WAIT(1); }
        else             { CP_WAIT(0); }
        __syncthreads();

        unsigned bb = sbase + (kt & 1) * BUF_BYTES;
        unsigned Ah = bb, Al = bb + A_BYTES;
        unsigned Bh = bb + 2 * A_BYTES, Bl = Bh + B_BYTES;

        int rsel = lane & 15, csel = (lane >> 4) * 8;
        #pragma unroll
        for (int kk = 0; kk < 2; kk++) {
            int kc = csel + kk * 16;
            unsigned ah[2][4], al[2][4], bh[2][4], bl[2][4];
            #pragma unroll
            for (int mt = 0; mt < 2; mt++) {
                unsigned off = (unsigned)((warpM + mt * 16 + rsel) * ASTRIDE + kc) * 2;
                ldm_x4(ah[mt][0], ah[mt][1], ah[mt][2], ah[mt][3], Ah + off);
                ldm_x4(al[mt][0], al[mt][1], al[mt][2], al[mt][3], Al + off);
            }
            #pragma unroll
            for (int np = 0; np < 2; np++) {
                unsigned off = (unsigned)((warpN + np * 16 + rsel) * ASTRIDE + kc) * 2;
                ldm_x4(bh[np][0], bh[np][1], bh[np][2], bh[np][3], Bh + off);
                ldm_x4(bl[np][0], bl[np][1], bl[np][2], bl[np][3], Bl + off);
            }
            #pragma unroll
            for (int mt = 0; mt < 2; mt++)
                #pragma unroll
                for (int nt = 0; nt < 4; nt++) {
                    int np = nt >> 1, hf = nt & 1;
                    mma_bf(acc[mt][nt], ah[mt], bh[np][hf], bh[np][hf + 2]);
                    mma_bf(acc[mt][nt], ah[mt], bl[np][hf], bl[np][hf + 2]);
                    mma_bf(acc[mt][nt], al[mt], bh[np][hf], bh[np][hf + 2]);
                }
        }
        __syncthreads();
    }

    // ---- epilogue: stage to smem (stride 68 floats, 16B-aligned rows)
    float* Ysm = (float*)dsm;
    #pragma unroll
    for (int mt = 0; mt < 2; mt++)
        #pragma unroll
        for (int nt = 0; nt < 4; nt++) {
            int r0 = warpM + mt * 16 + (lane >> 2);
            int cc = warpN + nt * 8 + (lane & 3) * 2;
            Ysm[r0 * YSTRIDE + cc]           = acc[mt][nt][0];
            Ysm[r0 * YSTRIDE + cc + 1]       = acc[mt][nt][1];
            Ysm[(r0 + 8) * YSTRIDE + cc]     = acc[mt][nt][2];
            Ysm[(r0 + 8) * YSTRIDE + cc + 1] = acc[mt][nt][3];
        }
    __syncthreads();
    #pragma unroll
    for (int i = 0; i < 8; i++) {
        int idx = i * 256 + t;          // 2048 float4 = 128 rows x 16
        int row = idx >> 4, c4 = (idx & 15) * 4;
        int o = o0 + row;
        if (o < O) {
            float4 v = *(float4*)(Ysm + row * YSTRIDE + c4);
            size_t goff = ((size_t)b * O + o) * HWN + p0 + c4;
            if (RESID) {
                float4 q = *(const float4*)(R + goff);
                v.x += q.x; v.y += q.y; v.z += q.z; v.w += q.w;
            }
            *(float4*)(Y + goff) = v;
        }
    }
}

// ---------------- LayerNorm -> transposed bf16 hi/lo ----------------
__global__ void ln_t(const float* __restrict__ X, const float* __restrict__ w,
                     const float* __restrict__ bia,
                     unsigned short* __restrict__ Hi, unsigned short* __restrict__ Lo) {
    int b = blockIdx.y;
    int p = blockIdx.x * 256 + threadIdx.x;
    const float* xp = X + (size_t)b * CC * HWN + p;
    float s = 0.f, s2 = 0.f;
    #pragma unroll 4
    for (int c = 0; c < CC; c++) { float v = xp[(size_t)c * HWN]; s += v; s2 += v * v; }
    const float invc = 1.f / CC;
    float mu = s * invc;
    float inv = rsqrtf(fmaxf(s2 * invc - mu * mu, 0.f) + EPSLN);
    unsigned short* hp = Hi + ((size_t)b * HWN + p) * CC;
    unsigned short* lp = Lo + ((size_t)b * HWN + p) * CC;
    #pragma unroll 2
    for (int c0 = 0; c0 < CC; c0 += 8) {
        float v[8];
        #pragma unroll
        for (int j = 0; j < 8; j++)
            v[j] = (xp[(size_t)(c0 + j) * HWN] - mu) * inv * w[c0 + j] + bia[c0 + j];
        uint4 hv, lv; cvt8(v, hv, lv);
        *(uint4*)(hp + c0) = hv;
        *(uint4*)(lp + c0) = lv;
    }
}

// ---------------- depthwise 3x3, 4 px/thread ----------------
__global__ void dwconv_dw(const float* __restrict__ X, const float* __restrict__ Wt,
                          float* __restrict__ Y, int Ctot) {
    int b = blockIdx.z, c = blockIdx.y;
    int p = (blockIdx.x * 256 + threadIdx.x) * 4;
    int h = p >> 7, wcol = p & 127;
    const float* xp = X + ((size_t)b * Ctot + c) * HWN;
    float kv[9];
    #pragma unroll
    for (int i = 0; i < 9; i++) kv[i] = Wt[(size_t)c * 9 + i];
    float a0 = 0, a1 = 0, a2 = 0, a3 = 0;
    #pragma unroll
    for (int dy = -1; dy <= 1; dy++) {
        int hh = h + dy;
        if (hh < 0 || hh >= HIMG) continue;
        const float* r = xp + hh * HIMG + wcol;
        float4 m = *(const float4*)r;
        float lf = (wcol > 0) ? r[-1] : 0.f;
        float rt = (wcol < 124) ? r[4] : 0.f;
        const float* k = kv + (dy + 1) * 3;
        a0 += k[0]*lf  + k[1]*m.x + k[2]*m.y;
        a1 += k[0]*m.x + k[1]*m.y + k[2]*m.z;
        a2 += k[0]*m.y + k[1]*m.z + k[2]*m.w;
        a3 += k[0]*m.z + k[1]*m.w + k[2]*rt;
    }
    *(float4*)(Y + ((size_t)b * Ctot + c) * HWN + p) = make_float4(a0, a1, a2, a3);
}

__global__ void dwconv_g2(const float* __restrict__ X, const float* __restrict__ Wt,
                          float* __restrict__ Y) {
    int b = blockIdx.z, o = blockIdx.y;
    int p = (blockIdx.x * 256 + threadIdx.x) * 4;
    int h = p >> 7, wcol = p & 127;
    int i0 = (o >> 1) << 1;
    const float* x0 = X + ((size_t)b * C2 + i0) * HWN;
    float kv[18];
    #pragma unroll
    for (int i = 0; i < 18; i++) kv[i] = Wt[(size_t)o * 18 + i];
    float a0 = 0, a1 = 0, a2 = 0, a3 = 0;
    #pragma unroll
    for (int ic = 0; ic < 2; ic++) {
        const float* xp = x0 + (size_t)ic * HWN;
        #pragma unroll
        for (int dy = -1; dy <= 1; dy++) {
            int hh = h + dy;
            if (hh < 0 || hh >= HIMG) continue;
            const float* r = xp + hh * HIMG + wcol;
            float4 m = *(const float4*)r;
            float lf = (wcol > 0) ? r[-1] : 0.f;
            float rt = (wcol < 124) ? r[4] : 0.f;
            const float* k = kv + ic * 9 + (dy + 1) * 3;
            a0 += k[0]*lf  + k[1]*m.x + k[2]*m.y;
            a1 += k[0]*m.x + k[1]*m.y + k[2]*m.z;
            a2 += k[0]*m.y + k[1]*m.z + k[2]*m.w;
            a3 += k[0]*m.z + k[1]*m.w + k[2]*rt;
        }
    }
    *(float4*)(Y + ((size_t)b * C2 + o) * HWN + p) = make_float4(a0, a1, a2, a3);
}

// ---------------- attention ----------------
__global__ void zero_S() {
    int i = blockIdx.x * 256 + threadIdx.x;
    if (i < 32 * CHD * CHD) g_S[i] = 0.f;
}

__global__ void rownorm_kernel() {
    int m = blockIdx.x, r = blockIdx.y;
    int b = m >> 3, br = (m >> 2) & 1, hh = m & 3;
    const float* base;
    if (r < CHD) {
        base = g_q + ((size_t)b * C2 + br * CC + hh * CHD + r) * HWN;
    } else {
        const float* src = br ? g_kv2 : g_kv1;
        base = src + ((size_t)b * C2 + hh * CHD + (r - CHD)) * HWN;
    }
    __shared__ float red[256];
    float s = 0.f;
    for (int i = threadIdx.x; i < HWN; i += 256) { float v = base[i]; s += v * v; }
    red[threadIdx.x] = s;
    __syncthreads();
    for (int st = 128; st > 0; st >>= 1) {
        if (threadIdx.x < st) red[threadIdx.x] += red[threadIdx.x + st];
        __syncthreads();
    }
    if (threadIdx.x == 0) g_nrm[m * 96 + r] = fmaxf(sqrtf(red[0]), 1e-12f);
}

__global__ void skernel() {
    int m = blockIdx.x, ns = blockIdx.y;
    int b = m >> 3, br = (m >> 2) & 1, hh = m & 3;
    const float* qb = g_q + ((size_t)b * C2 + br * CC + hh * CHD) * HWN;
    const float* kb = (br ? g_kv2 : g_kv1) + ((size_t)b * C2 + hh * CHD) * HWN;
    __shared__ float Qs[CHD][65];
    __shared__ float Ks[CHD][65];
    int t = threadIdx.x;
    int tx = t & 15, ty = t >> 4;
    float acc[3][3];
    #pragma unroll
    for (int i = 0; i < 3; i++)
        #pragma unroll
        for (int j = 0; j < 3; j++) acc[i][j] = 0.f;
    int nbeg = ns * 1024;
    for (int n0 = nbeg; n0 < nbeg + 1024; n0 += 64) {
        #pragma unroll
        for (int i = t; i < CHD * 64; i += 256) {
            int rr = i >> 6, cc = i & 63;
            Qs[rr][cc] = qb[(size_t)rr * HWN + n0 + cc];
            Ks[rr][cc] = kb[(size_t)rr * HWN + n0 + cc];
        }
        __syncthreads();
        #pragma unroll 8
        for (int kk = 0; kk < 64; kk++) {
            float qv[3], kvv[3];
            #pragma unroll
            for (int i = 0; i < 3; i++) qv[i] = Qs[ty + 16 * i][kk];
            #pragma unroll
            for (int j = 0; j < 3; j++) kvv[j] = Ks[tx + 16 * j][kk];
            #pragma unroll
            for (int i = 0; i < 3; i++)
                #pragma unroll
                for (int j = 0; j < 3; j++) acc[i][j] += qv[i] * kvv[j];
        }
        __syncthreads();
    }
    #pragma unroll
    for (int i = 0; i < 3; i++)
        #pragma unroll
        for (int j = 0; j < 3; j++)
            atomicAdd(&g_S[m * CHD * CHD + (ty + 16 * i) * CHD + (tx + 16 * j)], acc[i][j]);
}

__global__ void softmax_kernel(const float* __restrict__ t1, const float* __restrict__ t2) {
    int m = blockIdx.x;
    int c = threadIdx.x;
    if (c >= CHD) return;
    int br = (m >> 2) & 1, hh = m & 3;
    float tmp = (br ? t2 : t1)[hh];
    float nq = g_nrm[m * 96 + c];
    float* row = g_S + (size_t)m * CHD * CHD + c * CHD;
    float vals[CHD];
    float mx = -1e30f;
    #pragma unroll
    for (int d = 0; d < CHD; d++) {
        float v = row[d] / (nq * g_nrm[m * 96 + CHD + d]) * tmp;
        vals[d] = v;
        mx = fmaxf(mx, v);
    }
    float sum = 0.f;
    #pragma unroll
    for (int d = 0; d < CHD; d++) { vals[d] = __expf(vals[d] - mx); sum += vals[d]; }
    float inv = 1.f / sum;
    #pragma unroll
    for (int d = 0; d < CHD; d++) row[d] = vals[d] * inv;
}

// A·V -> transposed bf16 hi/lo output rows [p][384]
__global__ void av_t() {
    int m = blockIdx.x;
    int b = m >> 3, br = (m >> 2) & 1, hh = m & 3;
    __shared__ float As[CHD * CHD];
    for (int i = threadIdx.x; i < CHD * CHD; i += 128) As[i] = g_S[(size_t)m * CHD * CHD + i];
    __syncthreads();
    const float* vb = (br ? g_kv2 : g_kv1) + ((size_t)b * C2 + CC + hh * CHD) * HWN;
    int p = blockIdx.y * 256 + threadIdx.x;
    float acc0[CHD], acc1[CHD];
    #pragma unroll
    for (int c = 0; c < CHD; c++) { acc0[c] = 0.f; acc1[c] = 0.f; }
    for (int d = 0; d < CHD; d++) {
        float v0 = vb[(size_t)d * HWN + p];
        float v1 = vb[(size_t)d * HWN + p + 128];
        #pragma unroll
        for (int c = 0; c < CHD; c++) {
            float a = As[c * CHD + d];
            acc0[c] += a * v0;
            acc1[c] += a * v1;
        }
    }
    int off = br * CC + hh * CHD;
    unsigned short* h0 = xt_ao_hi + ((size_t)b * HWN + p) * C2 + off;
    unsigned short* l0 = xt_ao_lo + ((size_t)b * HWN + p) * C2 + off;
    unsigned short* h1 = h0 + (size_t)128 * C2;
    unsigned short* l1 = l0 + (size_t)128 * C2;
    #pragma unroll
    for (int c0 = 0; c0 < CHD; c0 += 8) {
        uint4 hv, lv;
        cvt8(acc0 + c0, hv, lv);
        *(uint4*)(h0 + c0) = hv; *(uint4*)(l0 + c0) = lv;
        cvt8(acc1 + c0, hv, lv);
        *(uint4*)(h1 + c0) = hv; *(uint4*)(l1 + c0) = lv;
    }
}

// ---------------- gated gelu -> transposed bf16 hi/lo (padded to 512) -------
__global__ void gelu_t() {
    int b = blockIdx.y;
    int p = blockIdx.x * 256 + threadIdx.x;
    const float* hp = g_hd + (size_t)b * HID2 * HWN + p;
    unsigned short* oh = xt_gg_hi + ((size_t)b * HWN + p) * GGPAD;
    unsigned short* ol = xt_gg_lo + ((size_t)b * HWN + p) * GGPAD;
    for (int c0 = 0; c0 < GGPAD; c0 += 8) {
        float v[8];
        #pragma unroll
        for (int j = 0; j < 8; j++) {
            int c = c0 + j;
            if (c < HIDC) {
                float a = hp[(size_t)c * HWN];
                float g = hp[(size_t)(c + HIDC) * HWN];
                float ge = 0.5f * a * (1.f + erff(a * 0.70710678118654752f));
                v[j] = ge * g;
            } else v[j] = 0.f;
        }
        uint4 hv, lv; cvt8(v, hv, lv);
        *(uint4*)(oh + c0) = hv;
        *(uint4*)(ol + c0) = lv;
    }
}

// ---------------- launch ----------------
extern "C" void kernel_launch(void* const* d_in, const int* in_sizes, int n_in,
                              void* d_out, int out_size) {
    const float* x       = (const float*)d_in[0];
    const float* kv1in   = (const float*)d_in[1];
    const float* kv2in   = (const float*)d_in[2];
    const float* n1w = (const float*)d_in[3];  const float* n1b = (const float*)d_in[4];
    const float* nk1w = (const float*)d_in[5]; const float* nk1b = (const float*)d_in[6];
    const float* nk2w = (const float*)d_in[7]; const float* nk2b = (const float*)d_in[8];
    const float* n2w = (const float*)d_in[9];  const float* n2b = (const float*)d_in[10];
    const float* q_w   = (const float*)d_in[11];
    const float* kv1_w = (const float*)d_in[12];
    const float* kv2_w = (const float*)d_in[13];
    const float* q_dw  = (const float*)d_in[14];
    const float* kv1_dw= (const float*)d_in[15];
    const float* kv2_dw= (const float*)d_in[16];
    const float* proj_w= (const float*)d_in[17];
    const float* temp1 = (const float*)d_in[18];
    const float* temp2 = (const float*)d_in[19];
    const float* pin_w = (const float*)d_in[20];
    const float* dw_w  = (const float*)d_in[21];
    const float* pout_w= (const float*)d_in[22];
    float* out = (float*)d_out;

    cudaFuncSetAttribute(gemm_mma<false>, cudaFuncAttributeMaxDynamicSharedMemorySize, GEMM_SMEM);
    cudaFuncSetAttribute(gemm_mma<true>,  cudaFuncAttributeMaxDynamicSharedMemorySize, GEMM_SMEM);

    float *p_qpre, *p_kv1pre, *p_kv2pre, *p_q, *p_kv1, *p_kv2, *p_x2, *p_h, *p_hd;
    cudaGetSymbolAddress((void**)&p_qpre, g_qpre);
    cudaGetSymbolAddress((void**)&p_kv1pre, g_kv1pre);
    cudaGetSymbolAddress((void**)&p_kv2pre, g_kv2pre);
    cudaGetSymbolAddress((void**)&p_q, g_q);
    cudaGetSymbolAddress((void**)&p_kv1, g_kv1);
    cudaGetSymbolAddress((void**)&p_kv2, g_kv2);
    cudaGetSymbolAddress((void**)&p_x2, g_x2);
    cudaGetSymbolAddress((void**)&p_h, g_h);
    cudaGetSymbolAddress((void**)&p_hd, g_hd);
    unsigned short *whi, *wlo, *ahi, *alo, *k1hi, *k1lo, *k2hi, *k2lo, *aohi, *aolo, *gghi, *gglo;
    cudaGetSymbolAddress((void**)&whi, g_whi);
    cudaGetSymbolAddress((void**)&wlo, g_wlo);
    cudaGetSymbolAddress((void**)&ahi, xt_a_hi);
    cudaGetSymbolAddress((void**)&alo, xt_a_lo);
    cudaGetSymbolAddress((void**)&k1hi, xt_k1_hi);
    cudaGetSymbolAddress((void**)&k1lo, xt_k1_lo);
    cudaGetSymbolAddress((void**)&k2hi, xt_k2_hi);
    cudaGetSymbolAddress((void**)&k2lo, xt_k2_lo);
    cudaGetSymbolAddress((void**)&aohi, xt_ao_hi);
    cudaGetSymbolAddress((void**)&aolo, xt_ao_lo);
    cudaGetSymbolAddress((void**)&gghi, xt_gg_hi);
    cudaGetSymbolAddress((void**)&gglo, xt_gg_lo);

    // weight conversion
    wconv<<<384, 24>>>(q_w,   whi + OFF_Q,   wlo + OFF_Q,   384, 192, 192);
    wconv<<<384, 24>>>(kv1_w, whi + OFF_K1,  wlo + OFF_K1,  384, 192, 192);
    wconv<<<384, 24>>>(kv2_w, whi + OFF_K2,  wlo + OFF_K2,  384, 192, 192);
    wconv<<<192, 48>>>(proj_w, whi + OFF_P,  wlo + OFF_P,   192, 384, 384);
    wconv<<<1020, 24>>>(pin_w, whi + OFF_PIN, wlo + OFF_PIN, 1020, 192, 192);
    wconv<<<192, 64>>>(pout_w, whi + OFF_PO, wlo + OFF_PO,  192, 510, 512);

    dim3 lnG(HWN / 256, BB);
    ln_t<<<lnG, 256>>>(x,     n1w,  n1b,  ahi,  alo);
    ln_t<<<lnG, 256>>>(kv1in, nk1w, nk1b, k1hi, k1lo);
    ln_t<<<lnG, 256>>>(kv2in, nk2w, nk2b, k2hi, k2lo);

    // 1x1 convs 192->384 on tensor cores (HMMA)
    dim3 gQ(HWN / 64, 3, BB);
    gemm_mma<false><<<gQ, 256, GEMM_SMEM>>>(whi + OFF_Q,  wlo + OFF_Q,  ahi,  alo,  nullptr, p_qpre,   384, 192);
    gemm_mma<false><<<gQ, 256, GEMM_SMEM>>>(whi + OFF_K1, wlo + OFF_K1, k1hi, k1lo, nullptr, p_kv1pre, 384, 192);
    gemm_mma<false><<<gQ, 256, GEMM_SMEM>>>(whi + OFF_K2, wlo + OFF_K2, k2hi, k2lo, nullptr, p_kv2pre, 384, 192);

    // 3x3 grouped / depthwise
    dim3 dG(HWN / 1024, C2, BB);
    dwconv_g2<<<dG, 256>>>(p_qpre, q_dw, p_q);
    dwconv_dw<<<dG, 256>>>(p_kv1pre, kv1_dw, p_kv1, C2);
    dwconv_dw<<<dG, 256>>>(p_kv2pre, kv2_dw, p_kv2, C2);

    // channel attention
    zero_S<<<(32 * CHD * CHD + 255) / 256, 256>>>();
    rownorm_kernel<<<dim3(32, 96), 256>>>();
    skernel<<<dim3(32, 16), 256>>>();
    softmax_kernel<<<32, 64>>>(temp1, temp2);
    av_t<<<dim3(32, HWN / 256), 128>>>();

    // proj (384 -> 192) + residual x
    dim3 gP(HWN / 64, 2, BB);
    gemm_mma<true><<<gP, 256, GEMM_SMEM>>>(whi + OFF_P, wlo + OFF_P, aohi, aolo, x, p_x2, 192, 384);

    // FFN
    ln_t<<<lnG, 256>>>(p_x2, n2w, n2b, ahi, alo);
    dim3 gIn(HWN / 64, 8, BB);
    gemm_mma<false><<<gIn, 256, GEMM_SMEM>>>(whi + OFF_PIN, wlo + OFF_PIN, ahi, alo, nullptr, p_h, 1020, 192);
    dim3 dG2(HWN / 1024, HID2, BB);
    dwconv_dw<<<dG2, 256>>>(p_h, dw_w, p_hd, HID2);
    gelu_t<<<lnG, 256>>>();
    gemm_mma<true><<<gP, 256, GEMM_SMEM>>>(whi + OFF_PO, wlo + OFF_PO, gghi, gglo, p_x2, out, 192, 512);
}

// round 6
// speedup vs baseline: 3.2558x; 1.2171x over previous
#include <cuda_runtime.h>
#include <cuda_bf16.h>
#include <math.h>

#define BB 4
#define CC 192
#define C2 384
#define HWN 16384
#define HIMG 128
#define CHD 48
#define HIDC 510
#define HID2 1020
#define GGPAD 512
#define EPSLN 1e-5f

__device__ __forceinline__ unsigned smem_u32(const void* p) {
    unsigned a;
    asm("{ .reg .u64 t; cvta.to.shared.u64 t, %1; cvt.u32.u64 %0, t; }"
        : "=r"(a) : "l"(p));
    return a;
}
#define CP_ASYNC16(dst, src) \
    asm volatile("cp.async.cg.shared.global [%0], [%1], 16;" :: "r"(dst), "l"(src))
#define CP_COMMIT() asm volatile("cp.async.commit_group;" ::: "memory")
#define CP_WAIT(n)  asm volatile("cp.async.wait_group %0;" :: "n"(n) : "memory")

__device__ __forceinline__ void ldm_x4(unsigned& r0, unsigned& r1, unsigned& r2, unsigned& r3,
                                       unsigned addr) {
    asm volatile("ldmatrix.sync.aligned.m8n8.x4.shared.b16 {%0,%1,%2,%3}, [%4];"
        : "=r"(r0), "=r"(r1), "=r"(r2), "=r"(r3) : "r"(addr));
}
__device__ __forceinline__ void ldm_x4_t(unsigned& r0, unsigned& r1, unsigned& r2, unsigned& r3,
                                         unsigned addr) {
    asm volatile("ldmatrix.sync.aligned.m8n8.x4.trans.shared.b16 {%0,%1,%2,%3}, [%4];"
        : "=r"(r0), "=r"(r1), "=r"(r2), "=r"(r3) : "r"(addr));
}
__device__ __forceinline__ void mma_bf(float* d, const unsigned* a, unsigned b0, unsigned b1) {
    asm volatile("mma.sync.aligned.m16n8k16.row.col.f32.bf16.bf16.f32 "
        "{%0,%1,%2,%3}, {%4,%5,%6,%7}, {%8,%9}, {%0,%1,%2,%3};"
        : "+f"(d[0]), "+f"(d[1]), "+f"(d[2]), "+f"(d[3])
        : "r"(a[0]), "r"(a[1]), "r"(a[2]), "r"(a[3]), "r"(b0), "r"(b1));
}

// ---------------- scratch ----------------
__device__ float g_qpre [BB*C2*HWN];
__device__ float g_kv1pre[BB*C2*HWN];
__device__ float g_kv2pre[BB*C2*HWN];
__device__ float g_q   [BB*C2*HWN];
__device__ float g_kv1 [BB*C2*HWN];
__device__ float g_kv2 [BB*C2*HWN];
__device__ float g_x2  [BB*CC*HWN];
__device__ float g_h   [BB*HID2*HWN];
__device__ float g_S   [32*CHD*CHD];
__device__ float g_nrm [32*2*CHD];     // sum-of-squares accumulators

// bf16 hi/lo activations, natural layout: [b][channel][pixel]
__device__ __align__(16) unsigned short xt_a_hi [BB*CC*HWN];
__device__ __align__(16) unsigned short xt_a_lo [BB*CC*HWN];
__device__ __align__(16) unsigned short xt_k1_hi[BB*CC*HWN];
__device__ __align__(16) unsigned short xt_k1_lo[BB*CC*HWN];
__device__ __align__(16) unsigned short xt_k2_hi[BB*CC*HWN];
__device__ __align__(16) unsigned short xt_k2_lo[BB*CC*HWN];
__device__ __align__(16) unsigned short xt_ao_hi[BB*C2*HWN];
__device__ __align__(16) unsigned short xt_ao_lo[BB*C2*HWN];
__device__ __align__(16) unsigned short xt_gg_hi[BB*GGPAD*HWN];
__device__ __align__(16) unsigned short xt_gg_lo[BB*GGPAD*HWN];
// converted weights (row-major [O][Cpad])
#define OFF_Q   0
#define OFF_K1  (384*192)
#define OFF_K2  (2*384*192)
#define OFF_P   (3*384*192)
#define OFF_PIN (3*384*192 + 192*384)
#define OFF_PO  (3*384*192 + 192*384 + 1020*192)
#define WTOT    (3*384*192 + 192*384 + 1020*192 + 192*512)
#define WPAD    (64*512)
__device__ __align__(16) unsigned short g_whi[WTOT + WPAD];
__device__ __align__(16) unsigned short g_wlo[WTOT + WPAD];

// ---------------- fp32 -> bf16 hi/lo helpers ----------------
__device__ __forceinline__ void cvt2(float a, float b, unsigned& h, unsigned& l) {
    __nv_bfloat16 ha = __float2bfloat16_rn(a), hb = __float2bfloat16_rn(b);
    h = (unsigned)__bfloat16_as_ushort(ha) | ((unsigned)__bfloat16_as_ushort(hb) << 16);
    __nv_bfloat16 la = __float2bfloat16_rn(a - __bfloat162float(ha));
    __nv_bfloat16 lb = __float2bfloat16_rn(b - __bfloat162float(hb));
    l = (unsigned)__bfloat16_as_ushort(la) | ((unsigned)__bfloat16_as_ushort(lb) << 16);
}
__device__ __forceinline__ void cvt8(const float* v, uint4& hv, uint4& lv) {
    unsigned h[4], l[4];
    #pragma unroll
    for (int i = 0; i < 4; i++) cvt2(v[2*i], v[2*i+1], h[i], l[i]);
    hv = make_uint4(h[0], h[1], h[2], h[3]);
    lv = make_uint4(l[0], l[1], l[2], l[3]);
}

__global__ void wconv(const float* __restrict__ W, unsigned short* __restrict__ Hi,
                      unsigned short* __restrict__ Lo, int O, int Cin, int Cpad) {
    int o = blockIdx.x;
    int c0 = threadIdx.x * 8;
    if (c0 >= Cpad) return;
    float v[8];
    #pragma unroll
    for (int j = 0; j < 8; j++) {
        int c = c0 + j;
        v[j] = (c < Cin) ? W[(size_t)o * Cin + c] : 0.f;
    }
    uint4 hv, lv; cvt8(v, hv, lv);
    *(uint4*)(Hi + (size_t)o * Cpad + c0) = hv;
    *(uint4*)(Lo + (size_t)o * Cpad + c0) = lv;
}

// ======================= HMMA GEMM ==========================================
// Y[b][o][p] = sum_c W[o][c] * X[b][c][p] (+ residual)
// W: [O][Cpad] row-major (k contig). X: [Cpad][HWN] natural layout, B loaded
// via ldmatrix.trans. BM=128, BN=64, BK=32. 8 warps 4x2, warp tile 32x32.
#define BK 32
#define ASTRIDE 40
#define PSTR 72                              // padded pixels per B smem row
#define A_BYTES (128 * ASTRIDE * 2)          // 10240
#define B_BYTES (BK * PSTR * 2)              // 4608
#define BUF_BYTES (2 * A_BYTES + 2 * B_BYTES)   // 29696
#define GEMM_SMEM (2 * BUF_BYTES)            // 59392
#define YSTRIDE 68

template<bool RESID>
__global__ __launch_bounds__(256)
void gemm_mma(const unsigned short* __restrict__ Whi, const unsigned short* __restrict__ Wlo,
              const unsigned short* __restrict__ Xhi, const unsigned short* __restrict__ Xlo,
              const float* __restrict__ R, float* __restrict__ Y, int O, int Cpad) {
    extern __shared__ char dsm[];
    unsigned sbase = smem_u32(dsm);
    int t = threadIdx.x, wid = t >> 5, lane = t & 31;
    int b  = blockIdx.z;
    int p0 = blockIdx.x * 64;
    int o0 = blockIdx.y * 128;
    int warpM = (wid >> 1) * 32;
    int warpN = (wid & 1) * 32;

    const unsigned short* WhiB = Whi + (size_t)o0 * Cpad;
    const unsigned short* WloB = Wlo + (size_t)o0 * Cpad;
    const unsigned short* XhiB = Xhi + (size_t)b * Cpad * HWN + p0;
    const unsigned short* XloB = Xlo + (size_t)b * Cpad * HWN + p0;

    int nk = Cpad / BK;

    auto fill = [&](int kt) {
        int buf = kt & 1;
        unsigned bb = sbase + buf * BUF_BYTES;
        int k0 = kt * BK;
        #pragma unroll
        for (int j = 0; j < 6; j++) {
            int ci = j * 256 + t;
            if (ci < 1024) {
                int m = ci & 511;
                int row = m >> 2, g = m & 3;
                const unsigned short* src = ((ci < 512) ? WhiB : WloB)
                                            + (size_t)row * Cpad + k0 + g * 8;
                unsigned dst = bb + ((ci < 512) ? 0u : A_BYTES)
                             + (unsigned)(row * ASTRIDE + g * 8) * 2;
                CP_ASYNC16(dst, src);
            } else {
                int m = ci - 1024;            // 0..511
                int mm = m & 255;
                int row = mm >> 3, g = mm & 7;
                const unsigned short* src = ((m < 256) ? XhiB : XloB)
                                            + (size_t)(k0 + row) * HWN + g * 8;
                unsigned dst = bb + 2 * A_BYTES + ((m < 256) ? 0u : B_BYTES)
                             + (unsigned)(row * PSTR + g * 8) * 2;
                CP_ASYNC16(dst, src);
            }
        }
        CP_COMMIT();
    };

    float acc[2][4][4];
    #pragma unroll
    for (int i = 0; i < 2; i++)
        #pragma unroll
        for (int j = 0; j < 4; j++)
            #pragma unroll
            for (int k = 0; k < 4; k++) acc[i][j][k] = 0.f;

    fill(0);

    int rsel = lane & 15, csel = (lane >> 4) * 8;
    // B trans-load lane mapping: rows = k, cols = pixels
    int bkr = (lane & 7) + ((lane >> 4) & 1) * 8;  // k row 0..15 within k16 step
    int bpc = ((lane >> 3) & 1) * 8;               // pixel sub-block 0/8

    for (int kt = 0; kt < nk; kt++) {
        if (kt + 1 < nk) { fill(kt + 1); CP_WAIT(1); }
        else             { CP_WAIT(0); }
        __syncthreads();

        unsigned bb = sbase + (kt & 1) * BUF_BYTES;
        unsigned Ah = bb, Al = bb + A_BYTES;
        unsigned Bh = bb + 2 * A_BYTES, Bl = Bh + B_BYTES;

        #pragma unroll
        for (int kk = 0; kk < 2; kk++) {
            int kc = csel + kk * 16;
            unsigned ah[2][4], al[2][4], bh[2][4], bl[2][4];
            #pragma unroll
            for (int mt = 0; mt < 2; mt++) {
                unsigned off = (unsigned)((warpM + mt * 16 + rsel) * ASTRIDE + kc) * 2;
                ldm_x4(ah[mt][0], ah[mt][1], ah[mt][2], ah[mt][3], Ah + off);
                ldm_x4(al[mt][0], al[mt][1], al[mt][2], al[mt][3], Al + off);
            }
            #pragma unroll
            for (int np = 0; np < 2; np++) {
                unsigned off = (unsigned)((kk * 16 + bkr) * PSTR + warpN + np * 16 + bpc) * 2;
                ldm_x4_t(bh[np][0], bh[np][1], bh[np][2], bh[np][3], Bh + off);
                ldm_x4_t(bl[np][0], bl[np][1], bl[np][2], bl[np][3], Bl + off);
            }
            #pragma unroll
            for (int mt = 0; mt < 2; mt++)
                #pragma unroll
                for (int nt = 0; nt < 4; nt++) {
                    int np = nt >> 1, hf = nt & 1;
                    mma_bf(acc[mt][nt], ah[mt], bh[np][hf], bh[np][hf + 2]);
                    mma_bf(acc[mt][nt], ah[mt], bl[np][hf], bl[np][hf + 2]);
                    mma_bf(acc[mt][nt], al[mt], bh[np][hf], bh[np][hf + 2]);
                }
        }
        __syncthreads();
    }

    // ---- epilogue: stage to smem, coalesced global write (+residual)
    float* Ysm = (float*)dsm;
    #pragma unroll
    for (int mt = 0; mt < 2; mt++)
        #pragma unroll
        for (int nt = 0; nt < 4; nt++) {
            int r0 = warpM + mt * 16 + (lane >> 2);
            int cc = warpN + nt * 8 + (lane & 3) * 2;
            Ysm[r0 * YSTRIDE + cc]           = acc[mt][nt][0];
            Ysm[r0 * YSTRIDE + cc + 1]       = acc[mt][nt][1];
            Ysm[(r0 + 8) * YSTRIDE + cc]     = acc[mt][nt][2];
            Ysm[(r0 + 8) * YSTRIDE + cc + 1] = acc[mt][nt][3];
        }
    __syncthreads();
    #pragma unroll
    for (int i = 0; i < 8; i++) {
        int idx = i * 256 + t;
        int row = idx >> 4, c4 = (idx & 15) * 4;
        int o = o0 + row;
        if (o < O) {
            float4 v = *(float4*)(Ysm + row * YSTRIDE + c4);
            size_t goff = ((size_t)b * O + o) * HWN + p0 + c4;
            if (RESID) {
                float4 q = *(const float4*)(R + goff);
                v.x += q.x; v.y += q.y; v.z += q.z; v.w += q.w;
            }
            *(float4*)(Y + goff) = v;
        }
    }
}

// ---------------- LayerNorm -> bf16 hi/lo [c][p], 2 px/thread ---------------
__global__ void ln_cp(const float* __restrict__ X, const float* __restrict__ w,
                      const float* __restrict__ bia,
                      unsigned short* __restrict__ Hi, unsigned short* __restrict__ Lo) {
    int b = blockIdx.y;
    int p = (blockIdx.x * 256 + threadIdx.x) * 2;
    const float* xp = X + (size_t)b * CC * HWN + p;
    float s0 = 0.f, s1 = 0.f, q0 = 0.f, q1 = 0.f;
    #pragma unroll 4
    for (int c = 0; c < CC; c++) {
        float2 v = *(const float2*)(xp + (size_t)c * HWN);
        s0 += v.x; s1 += v.y; q0 += v.x * v.x; q1 += v.y * v.y;
    }
    const float invc = 1.f / CC;
    float mu0 = s0 * invc, mu1 = s1 * invc;
    float iv0 = rsqrtf(fmaxf(q0 * invc - mu0 * mu0, 0.f) + EPSLN);
    float iv1 = rsqrtf(fmaxf(q1 * invc - mu1 * mu1, 0.f) + EPSLN);
    size_t base = (size_t)b * CC * HWN + p;
    #pragma unroll 4
    for (int c = 0; c < CC; c++) {
        float2 v = *(const float2*)(xp + (size_t)c * HWN);
        float wc = w[c], bc = bia[c];
        float o0 = (v.x - mu0) * iv0 * wc + bc;
        float o1 = (v.y - mu1) * iv1 * wc + bc;
        unsigned h, l; cvt2(o0, o1, h, l);
        *(unsigned*)(Hi + base + (size_t)c * HWN) = h;
        *(unsigned*)(Lo + base + (size_t)c * HWN) = l;
    }
}

// ---------------- depthwise 3x3, 4 px/thread ----------------
__global__ void dwconv_dw(const float* __restrict__ X, const float* __restrict__ Wt,
                          float* __restrict__ Y, int Ctot) {
    int b = blockIdx.z, c = blockIdx.y;
    int p = (blockIdx.x * 256 + threadIdx.x) * 4;
    int h = p >> 7, wcol = p & 127;
    const float* xp = X + ((size_t)b * Ctot + c) * HWN;
    float kv[9];
    #pragma unroll
    for (int i = 0; i < 9; i++) kv[i] = Wt[(size_t)c * 9 + i];
    float a0 = 0, a1 = 0, a2 = 0, a3 = 0;
    #pragma unroll
    for (int dy = -1; dy <= 1; dy++) {
        int hh = h + dy;
        if (hh < 0 || hh >= HIMG) continue;
        const float* r = xp + hh * HIMG + wcol;
        float4 m = *(const float4*)r;
        float lf = (wcol > 0) ? r[-1] : 0.f;
        float rt = (wcol < 124) ? r[4] : 0.f;
        const float* k = kv + (dy + 1) * 3;
        a0 += k[0]*lf  + k[1]*m.x + k[2]*m.y;
        a1 += k[0]*m.x + k[1]*m.y + k[2]*m.z;
        a2 += k[0]*m.y + k[1]*m.z + k[2]*m.w;
        a3 += k[0]*m.z + k[1]*m.w + k[2]*rt;
    }
    *(float4*)(Y + ((size_t)b * Ctot + c) * HWN + p) = make_float4(a0, a1, a2, a3);
}

__global__ void dwconv_g2(const float* __restrict__ X, const float* __restrict__ Wt,
                          float* __restrict__ Y) {
    int b = blockIdx.z, o = blockIdx.y;
    int p = (blockIdx.x * 256 + threadIdx.x) * 4;
    int h = p >> 7, wcol = p & 127;
    int i0 = (o >> 1) << 1;
    const float* x0 = X + ((size_t)b * C2 + i0) * HWN;
    float kv[18];
    #pragma unroll
    for (int i = 0; i < 18; i++) kv[i] = Wt[(size_t)o * 18 + i];
    float a0 = 0, a1 = 0, a2 = 0, a3 = 0;
    #pragma unroll
    for (int ic = 0; ic < 2; ic++) {
        const float* xp = x0 + (size_t)ic * HWN;
        #pragma unroll
        for (int dy = -1; dy <= 1; dy++) {
            int hh = h + dy;
            if (hh < 0 || hh >= HIMG) continue;
            const float* r = xp + hh * HIMG + wcol;
            float4 m = *(const float4*)r;
            float lf = (wcol > 0) ? r[-1] : 0.f;
            float rt = (wcol < 124) ? r[4] : 0.f;
            const float* k = kv + ic * 9 + (dy + 1) * 3;
            a0 += k[0]*lf  + k[1]*m.x + k[2]*m.y;
            a1 += k[0]*m.x + k[1]*m.y + k[2]*m.z;
            a2 += k[0]*m.y + k[1]*m.z + k[2]*m.w;
            a3 += k[0]*m.z + k[1]*m.w + k[2]*rt;
        }
    }
    *(float4*)(Y + ((size_t)b * C2 + o) * HWN + p) = make_float4(a0, a1, a2, a3);
}

// ---------------- fused FFN dwconv + gated gelu -> bf16 [c][p] --------------
__global__ void dwgelu(const float* __restrict__ X, const float* __restrict__ Wt,
                       unsigned short* __restrict__ Hi, unsigned short* __restrict__ Lo) {
    int b = blockIdx.z, c = blockIdx.y;   // c in [0, GGPAD)
    int p = (blockIdx.x * 256 + threadIdx.x) * 4;
    size_t oidx = ((size_t)b * GGPAD + c) * HWN + p;
    if (c >= HIDC) {
        *(uint2*)(Hi + oidx) = make_uint2(0, 0);
        *(uint2*)(Lo + oidx) = make_uint2(0, 0);
        return;
    }
    int h = p >> 7, wcol = p & 127;
    float va[8];   // [0..3]=a, [4..7]=g
    #pragma unroll
    for (int half = 0; half < 2; half++) {
        int ch = c + half * HIDC;
        const float* xp = X + ((size_t)b * HID2 + ch) * HWN;
        float kv[9];
        #pragma unroll
        for (int i = 0; i < 9; i++) kv[i] = Wt[(size_t)ch * 9 + i];
        float a0 = 0, a1 = 0, a2 = 0, a3 = 0;
        #pragma unroll
        for (int dy = -1; dy <= 1; dy++) {
            int hh = h + dy;
            if (hh < 0 || hh >= HIMG) continue;
            const float* r = xp + hh * HIMG + wcol;
            float4 m = *(const float4*)r;
            float lf = (wcol > 0) ? r[-1] : 0.f;
            float rt = (wcol < 124) ? r[4] : 0.f;
            const float* k = kv + (dy + 1) * 3;
            a0 += k[0]*lf  + k[1]*m.x + k[2]*m.y;
            a1 += k[0]*m.x + k[1]*m.y + k[2]*m.z;
            a2 += k[0]*m.y + k[1]*m.z + k[2]*m.w;
            a3 += k[0]*m.z + k[1]*m.w + k[2]*rt;
        }
        va[half*4+0] = a0; va[half*4+1] = a1; va[half*4+2] = a2; va[half*4+3] = a3;
    }
    float o[4];
    #pragma unroll
    for (int j = 0; j < 4; j++) {
        float a = va[j];
        float ge = 0.5f * a * (1.f + erff(a * 0.70710678118654752f));
        o[j] = ge * va[4+j];
    }
    unsigned h0, l0, h1, l1;
    cvt2(o[0], o[1], h0, l0);
    cvt2(o[2], o[3], h1, l1);
    *(uint2*)(Hi + oidx) = make_uint2(h0, h1);
    *(uint2*)(Lo + oidx) = make_uint2(l0, l1);
}

// ---------------- attention ----------------
__global__ void zero_attn() {
    int i = blockIdx.x * 256 + threadIdx.x;
    if (i < 32 * CHD * CHD) g_S[i] = 0.f;
    if (i < 32 * 96) g_nrm[i] = 0.f;
}

// logits + fused row sum-of-squares
__global__ void skernel() {
    int m = blockIdx.x, ns = blockIdx.y;
    int b = m >> 3, br = (m >> 2) & 1, hh = m & 3;
    const float* qb = g_q + ((size_t)b * C2 + br * CC + hh * CHD) * HWN;
    const float* kb = (br ? g_kv2 : g_kv1) + ((size_t)b * C2 + hh * CHD) * HWN;
    __shared__ float Qs[CHD][65];
    __shared__ float Ks[CHD][65];
    int t = threadIdx.x;
    int tx = t & 15, ty = t >> 4;
    float acc[3][3];
    #pragma unroll
    for (int i = 0; i < 3; i++)
        #pragma unroll
        for (int j = 0; j < 3; j++) acc[i][j] = 0.f;
    const float* nrow = (t < CHD) ? &Qs[t][0] : ((t < 96) ? &Ks[t - CHD][0] : (const float*)0);
    float nacc = 0.f;
    int nbeg = ns * 1024;
    for (int n0 = nbeg; n0 < nbeg + 1024; n0 += 64) {
        #pragma unroll
        for (int i = t; i < CHD * 64; i += 256) {
            int rr = i >> 6, cc = i & 63;
            Qs[rr][cc] = qb[(size_t)rr * HWN + n0 + cc];
            Ks[rr][cc] = kb[(size_t)rr * HWN + n0 + cc];
        }
        __syncthreads();
        if (nrow) {
            #pragma unroll 8
            for (int cc = 0; cc < 64; cc++) { float v = nrow[cc]; nacc += v * v; }
        }
        #pragma unroll 8
        for (int kk = 0; kk < 64; kk++) {
            float qv[3], kvv[3];
            #pragma unroll
            for (int i = 0; i < 3; i++) qv[i] = Qs[ty + 16 * i][kk];
            #pragma unroll
            for (int j = 0; j < 3; j++) kvv[j] = Ks[tx + 16 * j][kk];
            #pragma unroll
            for (int i = 0; i < 3; i++)
                #pragma unroll
                for (int j = 0; j < 3; j++) acc[i][j] += qv[i] * kvv[j];
        }
        __syncthreads();
    }
    #pragma unroll
    for (int i = 0; i < 3; i++)
        #pragma unroll
        for (int j = 0; j < 3; j++)
            atomicAdd(&g_S[m * CHD * CHD + (ty + 16 * i) * CHD + (tx + 16 * j)], acc[i][j]);
    if (t < 96) atomicAdd(&g_nrm[m * 96 + t], nacc);
}

__global__ void softmax_kernel(const float* __restrict__ t1, const float* __restrict__ t2) {
    int m = blockIdx.x;
    int c = threadIdx.x;
    __shared__ float nk[CHD];
    if (c < CHD) nk[c] = fmaxf(sqrtf(g_nrm[m * 96 + CHD + c]), 1e-12f);
    __syncthreads();
    if (c >= CHD) return;
    int br = (m >> 2) & 1, hh = m & 3;
    float tmp = (br ? t2 : t1)[hh];
    float nq = fmaxf(sqrtf(g_nrm[m * 96 + c]), 1e-12f);
    float* row = g_S + (size_t)m * CHD * CHD + c * CHD;
    float vals[CHD];
    float mx = -1e30f;
    #pragma unroll
    for (int d = 0; d < CHD; d++) {
        float v = row[d] / (nq * nk[d]) * tmp;
        vals[d] = v;
        mx = fmaxf(mx, v);
    }
    float sum = 0.f;
    #pragma unroll
    for (int d = 0; d < CHD; d++) { vals[d] = __expf(vals[d] - mx); sum += vals[d]; }
    float inv = 1.f / sum;
    #pragma unroll
    for (int d = 0; d < CHD; d++) row[d] = vals[d] * inv;
}

// A·V -> bf16 hi/lo [c][p], 2 adjacent px/thread
__global__ void av_cp() {
    int m = blockIdx.x;
    int b = m >> 3, br = (m >> 2) & 1, hh = m & 3;
    __shared__ float As[CHD * CHD];
    for (int i = threadIdx.x; i < CHD * CHD; i += 128) As[i] = g_S[(size_t)m * CHD * CHD + i];
    __syncthreads();
    const float* vb = (br ? g_kv2 : g_kv1) + ((size_t)b * C2 + CC + hh * CHD) * HWN;
    int p = blockIdx.y * 256 + threadIdx.x * 2;
    float acc0[CHD], acc1[CHD];
    #pragma unroll
    for (int c = 0; c < CHD; c++) { acc0[c] = 0.f; acc1[c] = 0.f; }
    for (int d = 0; d < CHD; d++) {
        float2 v = *(const float2*)(vb + (size_t)d * HWN + p);
        #pragma unroll
        for (int c = 0; c < CHD; c++) {
            float a = As[c * CHD + d];
            acc0[c] += a * v.x;
            acc1[c] += a * v.y;
        }
    }
    int off = br * CC + hh * CHD;
    size_t base = ((size_t)b * C2 + off) * HWN + p;
    #pragma unroll
    for (int c = 0; c < CHD; c++) {
        unsigned h, l; cvt2(acc0[c], acc1[c], h, l);
        *(unsigned*)(xt_ao_hi + base + (size_t)c * HWN) = h;
        *(unsigned*)(xt_ao_lo + base + (size_t)c * HWN) = l;
    }
}

// ---------------- launch ----------------
extern "C" void kernel_launch(void* const* d_in, const int* in_sizes, int n_in,
                              void* d_out, int out_size) {
    const float* x       = (const float*)d_in[0];
    const float* kv1in   = (const float*)d_in[1];
    const float* kv2in   = (const float*)d_in[2];
    const float* n1w = (const float*)d_in[3];  const float* n1b = (const float*)d_in[4];
    const float* nk1w = (const float*)d_in[5]; const float* nk1b = (const float*)d_in[6];
    const float* nk2w = (const float*)d_in[7]; const float* nk2b = (const float*)d_in[8];
    const float* n2w = (const float*)d_in[9];  const float* n2b = (const float*)d_in[10];
    const float* q_w   = (const float*)d_in[11];
    const float* kv1_w = (const float*)d_in[12];
    const float* kv2_w = (const float*)d_in[13];
    const float* q_dw  = (const float*)d_in[14];
    const float* kv1_dw= (const float*)d_in[15];
    const float* kv2_dw= (const float*)d_in[16];
    const float* proj_w= (const float*)d_in[17];
    const float* temp1 = (const float*)d_in[18];
    const float* temp2 = (const float*)d_in[19];
    const float* pin_w = (const float*)d_in[20];
    const float* dw_w  = (const float*)d_in[21];
    const float* pout_w= (const float*)d_in[22];
    float* out = (float*)d_out;

    cudaFuncSetAttribute(gemm_mma<false>, cudaFuncAttributeMaxDynamicSharedMemorySize, GEMM_SMEM);
    cudaFuncSetAttribute(gemm_mma<true>,  cudaFuncAttributeMaxDynamicSharedMemorySize, GEMM_SMEM);

    float *p_qpre, *p_kv1pre, *p_kv2pre, *p_q, *p_kv1, *p_kv2, *p_x2, *p_h;
    cudaGetSymbolAddress((void**)&p_qpre, g_qpre);
    cudaGetSymbolAddress((void**)&p_kv1pre, g_kv1pre);
    cudaGetSymbolAddress((void**)&p_kv2pre, g_kv2pre);
    cudaGetSymbolAddress((void**)&p_q, g_q);
    cudaGetSymbolAddress((void**)&p_kv1, g_kv1);
    cudaGetSymbolAddress((void**)&p_kv2, g_kv2);
    cudaGetSymbolAddress((void**)&p_x2, g_x2);
    cudaGetSymbolAddress((void**)&p_h, g_h);
    unsigned short *whi, *wlo, *ahi, *alo, *k1hi, *k1lo, *k2hi, *k2lo, *aohi, *aolo, *gghi, *gglo;
    cudaGetSymbolAddress((void**)&whi, g_whi);
    cudaGetSymbolAddress((void**)&wlo, g_wlo);
    cudaGetSymbolAddress((void**)&ahi, xt_a_hi);
    cudaGetSymbolAddress((void**)&alo, xt_a_lo);
    cudaGetSymbolAddress((void**)&k1hi, xt_k1_hi);
    cudaGetSymbolAddress((void**)&k1lo, xt_k1_lo);
    cudaGetSymbolAddress((void**)&k2hi, xt_k2_hi);
    cudaGetSymbolAddress((void**)&k2lo, xt_k2_lo);
    cudaGetSymbolAddress((void**)&aohi, xt_ao_hi);
    cudaGetSymbolAddress((void**)&aolo, xt_ao_lo);
    cudaGetSymbolAddress((void**)&gghi, xt_gg_hi);
    cudaGetSymbolAddress((void**)&gglo, xt_gg_lo);

    // weight conversion
    wconv<<<384, 24>>>(q_w,   whi + OFF_Q,   wlo + OFF_Q,   384, 192, 192);
    wconv<<<384, 24>>>(kv1_w, whi + OFF_K1,  wlo + OFF_K1,  384, 192, 192);
    wconv<<<384, 24>>>(kv2_w, whi + OFF_K2,  wlo + OFF_K2,  384, 192, 192);
    wconv<<<192, 48>>>(proj_w, whi + OFF_P,  wlo + OFF_P,   192, 384, 384);
    wconv<<<1020, 24>>>(pin_w, whi + OFF_PIN, wlo + OFF_PIN, 1020, 192, 192);
    wconv<<<192, 64>>>(pout_w, whi + OFF_PO, wlo + OFF_PO,  192, 510, 512);

    dim3 lnG(HWN / 512, BB);
    ln_cp<<<lnG, 256>>>(x,     n1w,  n1b,  ahi,  alo);
    ln_cp<<<lnG, 256>>>(kv1in, nk1w, nk1b, k1hi, k1lo);
    ln_cp<<<lnG, 256>>>(kv2in, nk2w, nk2b, k2hi, k2lo);

    // 1x1 convs 192->384 (HMMA)
    dim3 gQ(HWN / 64, 3, BB);
    gemm_mma<false><<<gQ, 256, GEMM_SMEM>>>(whi + OFF_Q,  wlo + OFF_Q,  ahi,  alo,  nullptr, p_qpre,   384, 192);
    gemm_mma<false><<<gQ, 256, GEMM_SMEM>>>(whi + OFF_K1, wlo + OFF_K1, k1hi, k1lo, nullptr, p_kv1pre, 384, 192);
    gemm_mma<false><<<gQ, 256, GEMM_SMEM>>>(whi + OFF_K2, wlo + OFF_K2, k2hi, k2lo, nullptr, p_kv2pre, 384, 192);

    // 3x3 grouped / depthwise
    dim3 dG(HWN / 1024, C2, BB);
    dwconv_g2<<<dG, 256>>>(p_qpre, q_dw, p_q);
    dwconv_dw<<<dG, 256>>>(p_kv1pre, kv1_dw, p_kv1, C2);
    dwconv_dw<<<dG, 256>>>(p_kv2pre, kv2_dw, p_kv2, C2);

    // channel attention (rownorm fused into skernel)
    zero_attn<<<300, 256>>>();
    skernel<<<dim3(32, 16), 256>>>();
    softmax_kernel<<<32, 64>>>(temp1, temp2);
    av_cp<<<dim3(32, HWN / 256), 128>>>();

    // proj (384 -> 192) + residual x
    dim3 gP(HWN / 64, 2, BB);
    gemm_mma<true><<<gP, 256, GEMM_SMEM>>>(whi + OFF_P, wlo + OFF_P, aohi, aolo, x, p_x2, 192, 384);

    // FFN
    ln_cp<<<lnG, 256>>>(p_x2, n2w, n2b, ahi, alo);
    dim3 gIn(HWN / 64, 8, BB);
    gemm_mma<false><<<gIn, 256, GEMM_SMEM>>>(whi + OFF_PIN, wlo + OFF_PIN, ahi, alo, nullptr, p_h, 1020, 192);
    dim3 dGG(HWN / 1024, GGPAD, BB);
    dwgelu<<<dGG, 256>>>(p_h, dw_w, gghi, gglo);
    gemm_mma<true><<<gP, 256, GEMM_SMEM>>>(whi + OFF_PO, wlo + OFF_PO, gghi, gglo, p_x2, out, 192, 512);
}